// round 2
// baseline (speedup 1.0000x reference)
#include <cuda_runtime.h>

#define ROWS 32
#define NTHREADS 256
#define TILE_STRIDE 1025
#define HBUF_STRIDE 65

typedef unsigned long long u64;

__device__ __forceinline__ u64 pack2(float lo, float hi) {
    u64 r; asm("mov.b64 %0, {%1, %2};" : "=l"(r) : "f"(lo), "f"(hi)); return r;
}
__device__ __forceinline__ void unpack2(u64 v, float& lo, float& hi) {
    asm("mov.b64 {%0, %1}, %2;" : "=f"(lo), "=f"(hi) : "l"(v));
}
__device__ __forceinline__ u64 fma2(u64 a, u64 b, u64 c) {
    u64 d; asm("fma.rn.f32x2 %0, %1, %2, %3;" : "=l"(d) : "l"(a), "l"(b), "l"(c)); return d;
}

__global__ __launch_bounds__(NTHREADS, 1) void mixer_kernel(
    const float* __restrict__ x,
    const float* __restrict__ W1a, const float* __restrict__ B1a,
    const float* __restrict__ W2a, const float* __restrict__ B2a,
    const float* __restrict__ W1b, const float* __restrict__ B1b,
    const float* __restrict__ W2b, const float* __restrict__ B2b,
    float* __restrict__ out)
{
    extern __shared__ float smem[];
    float* tile = smem;                          // [32][1025]
    float* hbuf = tile + ROWS * TILE_STRIDE;     // [32][65]
    float* w1   = hbuf + ROWS * HBUF_STRIDE;     // [32*64]
    float* w2   = w1 + 2048;                     // [64*32]
    float* b1   = w2 + 2048;                     // [64]
    float* b2   = b1 + 64;                       // [32]

    const int tid  = threadIdx.x;
    const int warp = tid >> 5;
    const int lane = tid & 31;
    const long row0 = (long)blockIdx.x * ROWS;

    // ---- load x tile (coalesced float4) ----
    {
        const float4* src = (const float4*)(x + row0 * 1024);
        for (int i = tid; i < ROWS * 256; i += NTHREADS) {
            int r = i >> 8, c4 = i & 255;
            float4 v = src[r * 256 + c4];
            float* d = &tile[r * TILE_STRIDE + c4 * 4];
            d[0] = v.x; d[1] = v.y; d[2] = v.z; d[3] = v.w;
        }
    }
    __syncthreads();

    #pragma unroll
    for (int layer = 0; layer < 2; ++layer) {
        const float* gW1 = layer ? W1b : W1a;
        const float* gB1 = layer ? B1b : B1a;
        const float* gW2 = layer ? W2b : W2a;
        const float* gB2 = layer ? B2b : B2a;
        const int cstep = layer ? 32 : 1;

        for (int n = 0; n < 32; ++n) {
            // ---- cooperative weight load for block n ----
            {
                const float4* s1 = (const float4*)(gW1 + n * 2048);
                const float4* s2 = (const float4*)(gW2 + n * 2048);
                float4* d1 = (float4*)w1;
                float4* d2 = (float4*)w2;
                for (int i = tid; i < 512; i += NTHREADS) d1[i] = s1[i];
                for (int i = tid; i < 512; i += NTHREADS) d2[i] = s2[i];
                if (tid < 64) b1[tid] = gB1[n * 64 + tid];
                else if (tid < 96) b2[tid - 64] = gB2[n * 32 + (tid - 64)];
            }
            __syncthreads();

            const int cbase = layer ? n : n * 32;
            const float* xrow = &tile[lane * TILE_STRIDE + cbase];

            // ---- matmul1 (32 -> 64): warp covers hidden cols [warp*8, warp*8+8) ----
            u64 acc[4];
            #pragma unroll
            for (int j = 0; j < 4; ++j)
                acc[j] = *(const u64*)&b1[warp * 8 + 2 * j];
            #pragma unroll
            for (int k = 0; k < 32; ++k) {
                float xv = xrow[k * cstep];            // conflict-free (stride 1025)
                u64 xp = pack2(xv, xv);
                const u64* wrow = (const u64*)&w1[k * 64 + warp * 8];  // broadcast
                #pragma unroll
                for (int j = 0; j < 4; ++j)
                    acc[j] = fma2(xp, wrow[j], acc[j]);
            }
            // ---- ELU + stage h ----
            float* hrow = &hbuf[lane * HBUF_STRIDE + warp * 8];
            #pragma unroll
            for (int j = 0; j < 4; ++j) {
                float lo, hi; unpack2(acc[j], lo, hi);
                hrow[2 * j]     = lo > 0.f ? lo : (__expf(lo) - 1.f);
                hrow[2 * j + 1] = hi > 0.f ? hi : (__expf(hi) - 1.f);
            }
            __syncthreads();

            // ---- matmul2 (64 -> 32): warp covers out cols [warp*4, warp*4+4) ----
            u64 acc2[2];
            acc2[0] = *(const u64*)&b2[warp * 4];
            acc2[1] = *(const u64*)&b2[warp * 4 + 2];
            const float* hr = &hbuf[lane * HBUF_STRIDE];
            #pragma unroll
            for (int k = 0; k < 64; ++k) {
                float hv = hr[k];                      // conflict-free (stride 65)
                u64 hp = pack2(hv, hv);
                const u64* wrow = (const u64*)&w2[k * 32 + warp * 4]; // broadcast
                acc2[0] = fma2(hp, wrow[0], acc2[0]);
                acc2[1] = fma2(hp, wrow[1], acc2[1]);
            }
            // ---- residual + in-place writeback ----
            float o0, o1, o2, o3;
            unpack2(acc2[0], o0, o1);
            unpack2(acc2[1], o2, o3);
            float* wb = &tile[lane * TILE_STRIDE + cbase];
            wb[(warp * 4 + 0) * cstep] += o0;
            wb[(warp * 4 + 1) * cstep] += o1;
            wb[(warp * 4 + 2) * cstep] += o2;
            wb[(warp * 4 + 3) * cstep] += o3;
            __syncthreads();
        }
    }

    // ---- store output (tile is already in final layout) ----
    {
        float4* dst = (float4*)(out + row0 * 1024);
        for (int i = tid; i < ROWS * 256; i += NTHREADS) {
            int r = i >> 8, c4 = i & 255;
            const float* s = &tile[r * TILE_STRIDE + c4 * 4];
            float4 v; v.x = s[0]; v.y = s[1]; v.z = s[2]; v.w = s[3];
            dst[r * 256 + c4] = v;
        }
    }
}

extern "C" void kernel_launch(void* const* d_in, const int* in_sizes, int n_in,
                              void* d_out, int out_size) {
    const float* x   = (const float*)d_in[0];
    const float* W1a = (const float*)d_in[1];
    const float* B1a = (const float*)d_in[2];
    const float* W2a = (const float*)d_in[3];
    const float* B2a = (const float*)d_in[4];
    const float* W1b = (const float*)d_in[5];
    const float* B1b = (const float*)d_in[6];
    const float* W2b = (const float*)d_in[7];
    const float* B2b = (const float*)d_in[8];
    float* out = (float*)d_out;

    int rows = in_sizes[0] / 1024;            // 16384
    int grid = rows / ROWS;                   // 512

    size_t smem_bytes = (size_t)(ROWS * TILE_STRIDE + ROWS * HBUF_STRIDE
                                 + 2048 + 2048 + 64 + 32) * sizeof(float);
    static int configured = -1;
    if (configured < 0) {
        cudaFuncSetAttribute(mixer_kernel,
                             cudaFuncAttributeMaxDynamicSharedMemorySize,
                             (int)smem_bytes);
        configured = 1;
    }

    mixer_kernel<<<grid, NTHREADS, smem_bytes>>>(
        x, W1a, B1a, W2a, B2a, W1b, B1b, W2b, B2b, out);
}

// round 3
// speedup vs baseline: 1.7886x; 1.7886x over previous
#include <cuda_runtime.h>

#define NTHREADS 256
#define ROWS 32
#define TILE_STRIDE 1025
#define HB_STRIDE 66
#define NB 4

typedef unsigned long long u64;

__device__ __forceinline__ u64 pack2(float lo, float hi) {
    u64 r; asm("mov.b64 %0, {%1, %2};" : "=l"(r) : "f"(lo), "f"(hi)); return r;
}
__device__ __forceinline__ void unpack2(u64 v, float& lo, float& hi) {
    asm("mov.b64 {%0, %1}, %2;" : "=f"(lo), "=f"(hi) : "l"(v));
}
__device__ __forceinline__ u64 fma2(u64 a, u64 b, u64 c) {
    u64 d; asm("fma.rn.f32x2 %0, %1, %2, %3;" : "=l"(d) : "l"(a), "l"(b), "l"(c)); return d;
}

// smem layout (floats):
//   tile : 32 * 1025                 = 32800
//   bufA : max(w1 4*2048, hbuf 4*32*66) = 8448   (w1 during mm1, hbuf during mm2)
//   w2s  : 4*2048                    = 8192
//   b1s  : 256
//   b2s  : 128
#define SM_TILE 0
#define SM_BUFA (32 * 1025)
#define SM_W2   (SM_BUFA + 8448)
#define SM_B1   (SM_W2 + 8192)
#define SM_B2   (SM_B1 + 256)
#define SM_TOTAL (SM_B2 + 128)

__global__ __launch_bounds__(NTHREADS, 1) void mixer_kernel(
    const float* __restrict__ x,
    const float* __restrict__ W1a, const float* __restrict__ B1a,
    const float* __restrict__ W2a, const float* __restrict__ B2a,
    const float* __restrict__ W1b, const float* __restrict__ B1b,
    const float* __restrict__ W2b, const float* __restrict__ B2b,
    float* __restrict__ out)
{
    extern __shared__ float smem[];
    float* tile = smem + SM_TILE;
    float* bufA = smem + SM_BUFA;
    float* w2s  = smem + SM_W2;
    float* b1s  = smem + SM_B1;
    float* b2s  = smem + SM_B2;

    const int tid   = threadIdx.x;
    const int warp  = tid >> 5;
    const int lane  = tid & 31;
    const int nb    = warp >> 1;        // sub-block 0..3 within group
    const int rhalf = warp & 1;         // row half
    const int rg    = lane >> 3;        // row group 0..3
    const int hg    = lane & 7;         // hidden/col group 0..7
    const int rbase = rhalf * 16 + rg * 4;
    const long row0 = (long)blockIdx.x * ROWS;

    // ---- load x tile (coalesced float4 from gmem, scalar STS due to odd stride) ----
    {
        const float4* src = (const float4*)(x + row0 * 1024);
        #pragma unroll
        for (int it = 0; it < 32; ++it) {
            int i = tid + it * NTHREADS;
            int r = i >> 8, c4 = i & 255;
            float4 v = src[r * 256 + c4];
            float* d = &tile[r * TILE_STRIDE + c4 * 4];
            d[0] = v.x; d[1] = v.y; d[2] = v.z; d[3] = v.w;
        }
    }

    const float* W1p[2] = {W1a, W1b};
    const float* W2p[2] = {W2a, W2b};
    const float* B1p[2] = {B1a, B1b};
    const float* B2p[2] = {B2a, B2b};

    float4 pf1[8], pf2[8];   // prefetch registers for next group's weights

    for (int gi = 0; gi < 16; ++gi) {
        const int layer = gi >> 3;
        const int g     = gi & 7;

        __syncthreads();   // previous group fully done with bufA/w2s (also covers x-tile load on gi==0)

        // ---- stage weights for this group ----
        {
            float4* d1 = (float4*)bufA;
            float4* d2 = (float4*)w2s;
            if (gi == 0) {
                const float4* s1 = (const float4*)W1p[0];
                const float4* s2 = (const float4*)W2p[0];
                #pragma unroll
                for (int j = 0; j < 8; ++j) {
                    d1[tid + 256 * j] = s1[tid + 256 * j];
                    d2[tid + 256 * j] = s2[tid + 256 * j];
                }
            } else {
                #pragma unroll
                for (int j = 0; j < 8; ++j) {
                    d1[tid + 256 * j] = pf1[j];
                    d2[tid + 256 * j] = pf2[j];
                }
            }
            b1s[tid] = B1p[layer][g * 256 + tid];
            if (tid < 128) b2s[tid] = B2p[layer][g * 128 + tid];
        }
        __syncthreads();

        // ---- prefetch next group's weights into registers (hidden behind compute) ----
        if (gi < 15) {
            const int l2 = (gi + 1) >> 3;
            const int g2 = (gi + 1) & 7;
            const float4* n1 = (const float4*)(W1p[l2] + (size_t)g2 * NB * 2048);
            const float4* n2 = (const float4*)(W2p[l2] + (size_t)g2 * NB * 2048);
            #pragma unroll
            for (int j = 0; j < 8; ++j) {
                pf1[j] = n1[tid + 256 * j];
                pf2[j] = n2[tid + 256 * j];
            }
        }

        const int cstep = layer ? 32 : 1;
        const int n     = g * NB + nb;
        const int cbase = layer ? n : n * 32;

        // ---- matmul1: (4 rows) x (8 hidden) per thread, hidden cols = 2*hg + 16*j ----
        u64 acc[4][4];
        {
            const float* b1p = b1s + nb * 64 + 2 * hg;
            #pragma unroll
            for (int j = 0; j < 4; ++j) {
                u64 bv = *(const u64*)(b1p + 16 * j);
                acc[0][j] = bv; acc[1][j] = bv; acc[2][j] = bv; acc[3][j] = bv;
            }
        }
        {
            const float* w1p  = bufA + nb * 2048 + 2 * hg;
            const float* xrow = tile + rbase * TILE_STRIDE + cbase;
            #pragma unroll 8
            for (int k = 0; k < 32; ++k) {
                float xv0 = xrow[0 * TILE_STRIDE + k * cstep];
                float xv1 = xrow[1 * TILE_STRIDE + k * cstep];
                float xv2 = xrow[2 * TILE_STRIDE + k * cstep];
                float xv3 = xrow[3 * TILE_STRIDE + k * cstep];
                u64 xp0 = pack2(xv0, xv0), xp1 = pack2(xv1, xv1);
                u64 xp2 = pack2(xv2, xv2), xp3 = pack2(xv3, xv3);
                const float* wk = w1p + k * 64;
                #pragma unroll
                for (int j = 0; j < 4; ++j) {
                    u64 wv = *(const u64*)(wk + 16 * j);
                    acc[0][j] = fma2(xp0, wv, acc[0][j]);
                    acc[1][j] = fma2(xp1, wv, acc[1][j]);
                    acc[2][j] = fma2(xp2, wv, acc[2][j]);
                    acc[3][j] = fma2(xp3, wv, acc[3][j]);
                }
            }
        }
        __syncthreads();   // all threads done reading w1 before bufA becomes hbuf

        // ---- ELU + stage h in bufA (stride 66, u64-aligned) ----
        {
            float* hb = bufA + nb * (32 * HB_STRIDE) + 2 * hg;
            #pragma unroll
            for (int i = 0; i < 4; ++i) {
                float* hrow = hb + (rbase + i) * HB_STRIDE;
                #pragma unroll
                for (int j = 0; j < 4; ++j) {
                    float lo, hi; unpack2(acc[i][j], lo, hi);
                    lo = lo > 0.f ? lo : (__expf(lo) - 1.f);
                    hi = hi > 0.f ? hi : (__expf(hi) - 1.f);
                    *(u64*)(hrow + 16 * j) = pack2(lo, hi);
                }
            }
        }
        __syncthreads();

        // ---- matmul2: (4 rows) x (4 out cols) per thread; cg = lane&7 ----
        {
            const int cg = hg;
            u64 acc2[4][2];
            const float* b2p = b2s + nb * 32 + cg * 4;
            const float* xr  = tile + rbase * TILE_STRIDE + cbase;
            const u64 ONE = pack2(1.f, 1.f);
            #pragma unroll
            for (int i = 0; i < 4; ++i) {
                #pragma unroll
                for (int m = 0; m < 2; ++m) {
                    u64 bv = *(const u64*)(b2p + 2 * m);
                    int c0 = cg * 4 + 2 * m;
                    float r0v = xr[i * TILE_STRIDE + c0 * cstep];
                    float r1v = xr[i * TILE_STRIDE + (c0 + 1) * cstep];
                    acc2[i][m] = fma2(ONE, bv, pack2(r0v, r1v));  // bias + residual
                }
            }
            const float* hrd = bufA + nb * (32 * HB_STRIDE) + rbase * HB_STRIDE;
            const float* w2p = w2s + nb * 2048 + cg * 4;
            #pragma unroll 8
            for (int k = 0; k < 64; ++k) {
                float h0 = hrd[0 * HB_STRIDE + k];
                float h1 = hrd[1 * HB_STRIDE + k];
                float h2 = hrd[2 * HB_STRIDE + k];
                float h3 = hrd[3 * HB_STRIDE + k];
                u64 hp0 = pack2(h0, h0), hp1 = pack2(h1, h1);
                u64 hp2 = pack2(h2, h2), hp3 = pack2(h3, h3);
                const float* wk = w2p + k * 32;
                u64 w0 = *(const u64*)(wk + 0);
                u64 w1v = *(const u64*)(wk + 2);
                acc2[0][0] = fma2(hp0, w0, acc2[0][0]);
                acc2[0][1] = fma2(hp0, w1v, acc2[0][1]);
                acc2[1][0] = fma2(hp1, w0, acc2[1][0]);
                acc2[1][1] = fma2(hp1, w1v, acc2[1][1]);
                acc2[2][0] = fma2(hp2, w0, acc2[2][0]);
                acc2[2][1] = fma2(hp2, w1v, acc2[2][1]);
                acc2[3][0] = fma2(hp3, w0, acc2[3][0]);
                acc2[3][1] = fma2(hp3, w1v, acc2[3][1]);
            }
            // pure stores (residual already folded in)
            float* wbp = tile + rbase * TILE_STRIDE + cbase;
            #pragma unroll
            for (int i = 0; i < 4; ++i) {
                #pragma unroll
                for (int m = 0; m < 2; ++m) {
                    float lo, hi; unpack2(acc2[i][m], lo, hi);
                    int c0 = cg * 4 + 2 * m;
                    wbp[i * TILE_STRIDE + c0 * cstep]       = lo;
                    wbp[i * TILE_STRIDE + (c0 + 1) * cstep] = hi;
                }
            }
        }
    }

    __syncthreads();

    // ---- store output (tile already in final layout) ----
    {
        float4* dst = (float4*)(out + row0 * 1024);
        #pragma unroll
        for (int it = 0; it < 32; ++it) {
            int i = tid + it * NTHREADS;
            int r = i >> 8, c4 = i & 255;
            const float* s = &tile[r * TILE_STRIDE + c4 * 4];
            float4 v; v.x = s[0]; v.y = s[1]; v.z = s[2]; v.w = s[3];
            dst[r * 256 + c4] = v;
        }
    }
}

extern "C" void kernel_launch(void* const* d_in, const int* in_sizes, int n_in,
                              void* d_out, int out_size) {
    const float* x   = (const float*)d_in[0];
    const float* W1a = (const float*)d_in[1];
    const float* B1a = (const float*)d_in[2];
    const float* W2a = (const float*)d_in[3];
    const float* B2a = (const float*)d_in[4];
    const float* W1b = (const float*)d_in[5];
    const float* B1b = (const float*)d_in[6];
    const float* W2b = (const float*)d_in[7];
    const float* B2b = (const float*)d_in[8];
    float* out = (float*)d_out;

    int rows = in_sizes[0] / 1024;      // 16384
    int grid = rows / ROWS;             // 512

    size_t smem_bytes = (size_t)SM_TOTAL * sizeof(float);   // ~199 KB
    static int configured = -1;
    if (configured < 0) {
        cudaFuncSetAttribute(mixer_kernel,
                             cudaFuncAttributeMaxDynamicSharedMemorySize,
                             (int)smem_bytes);
        configured = 1;
    }

    mixer_kernel<<<grid, NTHREADS, smem_bytes>>>(
        x, W1a, B1a, W2a, B2a, W1b, B1b, W2b, B2b, out);
}